// round 2
// baseline (speedup 1.0000x reference)
#include <cuda_runtime.h>
#include <math.h>

#define EPS 1e-8f
#define RAD2DEG 57.295779513082320876798154814105f

// Inputs: data [N,64] f32, lab [N,3] f32, W [64,3] f32, b [3] f32
// Output: [N] f32
//
// Layout: 8 lanes cooperate per row (4 rows per warp). Lane j loads the
// float4 at byte offsets j*16 and 128 + j*16 of its row, so each warp-wide
// LDG.128 covers exactly four full 128B cache lines (4 wavefronts, zero
// sector waste). Partial dots reduced via shfl_xor within the 8-lane group.

__global__ __launch_bounds__(256) void cosine_loss_kernel(
    const float* __restrict__ data,
    const float* __restrict__ lab,
    const float* __restrict__ W,
    const float* __restrict__ b,
    float* __restrict__ out,
    int N)
{
    // W transposed to [3][64] in shared, read as float4.
    __shared__ __align__(16) float sW[3][64];
    __shared__ float sb[3];

    int t = threadIdx.x;
    if (t < 192) {
        int k = t / 3;       // input dim
        int c = t % 3;       // output channel
        sW[c][k] = W[t];     // W[k*3+c]
    }
    if (t >= 192 && t < 195) sb[t - 192] = b[t - 192];
    __syncthreads();

    const int warp = t >> 5;
    const int lane = t & 31;
    const int g    = lane >> 3;   // group within warp: 0..3 (one row each)
    const int j    = lane & 7;    // lane within group: 0..7

    // 32 rows per block (8 warps x 4 rows)
    int row = blockIdx.x * 32 + warp * 4 + g;
    if (row >= N) return;

    const float4* __restrict__ dv =
        reinterpret_cast<const float4*>(data) + (size_t)row * 16;

    // Two coalesced 128B-line loads per warp-instruction.
    float4 d0 = __ldcs(&dv[j]);
    float4 d1 = __ldcs(&dv[8 + j]);

    const float4* __restrict__ w0v = reinterpret_cast<const float4*>(sW[0]);
    const float4* __restrict__ w1v = reinterpret_cast<const float4*>(sW[1]);
    const float4* __restrict__ w2v = reinterpret_cast<const float4*>(sW[2]);

    float4 wa, wb2;
    float acc0, acc1, acc2;

    wa = w0v[j]; wb2 = w0v[8 + j];
    acc0 = d0.x * wa.x  + d0.y * wa.y  + d0.z * wa.z  + d0.w * wa.w
         + d1.x * wb2.x + d1.y * wb2.y + d1.z * wb2.z + d1.w * wb2.w;
    wa = w1v[j]; wb2 = w1v[8 + j];
    acc1 = d0.x * wa.x  + d0.y * wa.y  + d0.z * wa.z  + d0.w * wa.w
         + d1.x * wb2.x + d1.y * wb2.y + d1.z * wb2.z + d1.w * wb2.w;
    wa = w2v[j]; wb2 = w2v[8 + j];
    acc2 = d0.x * wa.x  + d0.y * wa.y  + d0.z * wa.z  + d0.w * wa.w
         + d1.x * wb2.x + d1.y * wb2.y + d1.z * wb2.z + d1.w * wb2.w;

    // Reduce the 3 accumulators across the 8-lane group.
    #pragma unroll
    for (int off = 4; off >= 1; off >>= 1) {
        acc0 += __shfl_xor_sync(0xFFFFFFFFu, acc0, off);
        acc1 += __shfl_xor_sync(0xFFFFFFFFu, acc1, off);
        acc2 += __shfl_xor_sync(0xFFFFFFFFu, acc2, off);
    }

    if (j == 0) {
        float p0 = acc0 + sb[0];
        float p1 = acc1 + sb[1];
        float p2 = acc2 + sb[2];

        // F.normalize(pred, dim=1)
        float n = sqrtf(p0 * p0 + p1 * p1 + p2 * p2);
        float inv = 1.0f / fmaxf(n, EPS);
        float pn0 = p0 * inv, pn1 = p1 * inv, pn2 = p2 * inv;

        const float* lr = lab + (size_t)row * 3;
        float l0 = __ldcs(&lr[0]);
        float l1 = __ldcs(&lr[1]);
        float l2 = __ldcs(&lr[2]);

        float dot = pn0 * l0 + pn1 * l1 + pn2 * l2;
        float na = fmaxf(sqrtf(pn0 * pn0 + pn1 * pn1 + pn2 * pn2), EPS);
        float nb = fmaxf(sqrtf(l0 * l0 + l1 * l1 + l2 * l2), EPS);
        float cosv = dot / (na * nb);

        float loss = acosf(cosv) * RAD2DEG;
        if (isnan(loss)) loss = 0.0f;

        out[row] = loss;
    }
}

extern "C" void kernel_launch(void* const* d_in, const int* in_sizes, int n_in,
                              void* d_out, int out_size)
{
    const float* data = (const float*)d_in[0];
    const float* lab  = (const float*)d_in[1];
    const float* W    = (const float*)d_in[2];
    const float* b    = (const float*)d_in[3];
    float* out = (float*)d_out;

    int N = in_sizes[0] / 64;
    int rows_per_block = 32;                 // 256 threads / 8 lanes-per-row
    int blocks = (N + rows_per_block - 1) / rows_per_block;
    cosine_loss_kernel<<<blocks, 256>>>(data, lab, W, b, out, N);
}

// round 3
// speedup vs baseline: 1.9630x; 1.9630x over previous
#include <cuda_runtime.h>
#include <math.h>

#define EPS 1e-8f
#define RAD2DEG 57.295779513082320876798154814105f

#define THREADS 128
#define ROWS 128            // rows per block == threads (one row per thread)
#define STRIDE 68           // smem row stride in floats (68 % 32 == 4 -> conflict-free .128 access)

// Inputs: data [N,64] f32, lab [N,3] f32, W [64,3] f32, b [3] f32
// Output: [N] f32
//
// Stage a 128x64 data tile into shared with fully coalesced LDG.128
// (minimum L1 wavefronts, 16 outstanding loads/thread), then each thread
// computes one row entirely from shared memory (no shuffles).

__global__ __launch_bounds__(THREADS) void cosine_loss_kernel(
    const float* __restrict__ data,
    const float* __restrict__ lab,
    const float* __restrict__ W,
    const float* __restrict__ b,
    float* __restrict__ out,
    int N)
{
    __shared__ __align__(16) float sData[ROWS * STRIDE];   // 34816 B
    __shared__ __align__(16) float sW[3][64];
    __shared__ float sb[3];

    const int t = threadIdx.x;

    // Stage W transposed to [3][64] and b.
    {
        int i = t;
        if (i < 192) {
            int k = i / 3, c = i % 3;
            sW[c][k] = W[i];                 // W row-major [64,3]
        }
        i = t + 128;
        if (i < 192) {
            int k = i / 3, c = i % 3;
            sW[c][k] = W[i];
        }
        if (t < 3) sb[t] = b[t];
    }

    const int row0 = blockIdx.x * ROWS;
    const int rows_here = min(ROWS, N - row0);
    const int nvec = rows_here * 16;         // float4s in this tile

    // Coalesced tile load: 16 float4 per thread, consecutive across the block.
    const float4* __restrict__ gsrc =
        reinterpret_cast<const float4*>(data) + (size_t)row0 * 16;
    #pragma unroll
    for (int i = 0; i < 16; ++i) {
        int idx = i * THREADS + t;           // 0..2047
        if (idx < nvec) {
            float4 v = __ldcs(&gsrc[idx]);
            int r = idx >> 4;                // local row
            int c = idx & 15;                // float4 within row
            *reinterpret_cast<float4*>(&sData[r * STRIDE + c * 4]) = v;
        }
    }

    // Load lab for this thread's row while loads are in flight.
    const int row = row0 + t;
    float l0 = 0.f, l1 = 0.f, l2 = 0.f;
    if (row < N) {
        const float* lr = lab + (size_t)row * 3;
        l0 = __ldg(&lr[0]);
        l1 = __ldg(&lr[1]);
        l2 = __ldg(&lr[2]);
    }

    __syncthreads();

    if (row >= N) return;

    const float4* __restrict__ dv =
        reinterpret_cast<const float4*>(&sData[t * STRIDE]);
    const float4* __restrict__ w0v = reinterpret_cast<const float4*>(sW[0]);
    const float4* __restrict__ w1v = reinterpret_cast<const float4*>(sW[1]);
    const float4* __restrict__ w2v = reinterpret_cast<const float4*>(sW[2]);

    float acc0 = 0.f, acc1 = 0.f, acc2 = 0.f;
    #pragma unroll
    for (int k = 0; k < 16; ++k) {
        float4 d  = dv[k];
        float4 w0 = w0v[k];
        float4 w1 = w1v[k];
        float4 w2 = w2v[k];
        acc0 += d.x * w0.x + d.y * w0.y + d.z * w0.z + d.w * w0.w;
        acc1 += d.x * w1.x + d.y * w1.y + d.z * w1.z + d.w * w1.w;
        acc2 += d.x * w2.x + d.y * w2.y + d.z * w2.z + d.w * w2.w;
    }

    float p0 = acc0 + sb[0];
    float p1 = acc1 + sb[1];
    float p2 = acc2 + sb[2];

    // F.normalize(pred, dim=1)
    float n = sqrtf(p0 * p0 + p1 * p1 + p2 * p2);
    float inv = 1.0f / fmaxf(n, EPS);
    float pn0 = p0 * inv, pn1 = p1 * inv, pn2 = p2 * inv;

    float dot = pn0 * l0 + pn1 * l1 + pn2 * l2;
    float na = fmaxf(sqrtf(pn0 * pn0 + pn1 * pn1 + pn2 * pn2), EPS);
    float nb = fmaxf(sqrtf(l0 * l0 + l1 * l1 + l2 * l2), EPS);
    float cosv = dot / (na * nb);

    float loss = acosf(cosv) * RAD2DEG;
    if (isnan(loss)) loss = 0.0f;

    out[row] = loss;
}

extern "C" void kernel_launch(void* const* d_in, const int* in_sizes, int n_in,
                              void* d_out, int out_size)
{
    const float* data = (const float*)d_in[0];
    const float* lab  = (const float*)d_in[1];
    const float* W    = (const float*)d_in[2];
    const float* b    = (const float*)d_in[3];
    float* out = (float*)d_out;

    int N = in_sizes[0] / 64;
    int blocks = (N + ROWS - 1) / ROWS;
    cosine_loss_kernel<<<blocks, THREADS>>>(data, lab, W, b, out, N);
}

// round 5
// speedup vs baseline: 2.0934x; 1.0664x over previous
#include <cuda_runtime.h>
#include <cstdint>
#include <math.h>

#define EPS 1e-8f
#define RAD2DEG 57.295779513082320876798154814105f

#define THREADS    128
#define TILE_ROWS  128
#define HALF_VEC   8          // float4 per row per half-tile (32 floats)
#define SSTRIDE    36         // floats per row in stage buffer (32 + 4 pad)

// Inputs: data [N,64] f32, lab [N,3] f32, W [64,3] f32, b [3] f32 ; out [N] f32
//
// Persistent blocks, grid-stride over 128-row tiles. Each tile is split into
// two 32-column half-tiles staged via cp.async.cg into ping-pong shared
// buffers; half-tile i+2 streams in while half-tile i is consumed, so DRAM
// loads stay in flight across the whole kernel.

__device__ __forceinline__ void cp_async16(unsigned int dst, const void* src) {
    asm volatile("cp.async.cg.shared.global [%0], [%1], 16;\n"
                 :: "r"(dst), "l"(src));
}
__device__ __forceinline__ void cp_commit() {
    asm volatile("cp.async.commit_group;\n");
}
template <int n>
__device__ __forceinline__ void cp_wait() {
    asm volatile("cp.async.wait_group %0;\n" :: "n"(n));
}

__global__ __launch_bounds__(THREADS) void cosine_loss_kernel(
    const float* __restrict__ data,
    const float* __restrict__ lab,
    const float* __restrict__ W,
    const float* __restrict__ b,
    float* __restrict__ out,
    int N, int ntiles)
{
    __shared__ __align__(16) float sbuf[2][TILE_ROWS * SSTRIDE];  // 2 x 18 KB
    __shared__ __align__(16) float sW[3][64];
    __shared__ float sb[3];

    const int t = threadIdx.x;

    // Stage W transposed to [3][64] and b (visible after first barrier).
    if (t < 192) { int k = t / 3, c = t % 3; sW[c][k] = W[t]; }
    {
        int i = t + 128;
        if (i < 192) { int k = i / 3, c = i % 3; sW[c][k] = W[i]; }
    }
    if (t < 3) sb[t] = b[t];

    // This block's work: tiles blockIdx.x, blockIdx.x+gridDim.x, ...
    // Items enumerate (tile, half): item = 2*tile_slot + half.
    const int nslots = (ntiles - blockIdx.x + (int)gridDim.x - 1) / (int)gridDim.x;
    const int nitems = 2 * nslots;
    if (nitems == 0) return;

    // Stage one (tile, half) item into sbuf[item&1].
    auto prefetch = [&](int item) {
        int slot = item >> 1;
        int half = item & 1;
        int tile = blockIdx.x + slot * gridDim.x;
        int row0 = tile * TILE_ROWS;
        const float4* gsrc = reinterpret_cast<const float4*>(data);
        unsigned int sdst =
            (unsigned int)__cvta_generic_to_shared(&sbuf[item & 1][0]);
        #pragma unroll
        for (int j = 0; j < HALF_VEC; ++j) {
            int v = j * THREADS + t;          // 0..1023 float4s in half-tile
            int r = v >> 3;                   // local row
            int c = v & 7;                    // float4 within half-row
            int row = row0 + r;
            if (row < N) {
                const float4* src = &gsrc[(size_t)row * 16 + half * 8 + c];
                cp_async16(sdst + (unsigned int)((r * SSTRIDE + c * 4) * 4), src);
            }
        }
        cp_commit();
    };

    // Prime the pipeline.
    prefetch(0);
    if (nitems > 1) prefetch(1); else cp_commit();

    const float4* __restrict__ w0v = reinterpret_cast<const float4*>(sW[0]);
    const float4* __restrict__ w1v = reinterpret_cast<const float4*>(sW[1]);
    const float4* __restrict__ w2v = reinterpret_cast<const float4*>(sW[2]);

    float acc0 = 0.f, acc1 = 0.f, acc2 = 0.f;
    float l0 = 0.f, l1 = 0.f, l2 = 0.f;
    int cur_row = -1;

    for (int item = 0; item < nitems; ++item) {
        cp_wait<1>();
        __syncthreads();   // buffer (item&1) fully staged and visible

        const int slot = item >> 1;
        const int half = item & 1;
        const int tile = blockIdx.x + slot * gridDim.x;
        const int row  = tile * TILE_ROWS + t;
        const bool live = (row < N);

        const float4* __restrict__ dv =
            reinterpret_cast<const float4*>(&sbuf[item & 1][t * SSTRIDE]);

        if (half == 0) {
            acc0 = acc1 = acc2 = 0.f;
            cur_row = row;
            if (live) {       // prefetch lab early to hide latency
                const float* lr = lab + (size_t)row * 3;
                l0 = __ldg(&lr[0]); l1 = __ldg(&lr[1]); l2 = __ldg(&lr[2]);
            }
        }

        #pragma unroll
        for (int k = 0; k < HALF_VEC; ++k) {
            float4 d  = dv[k];
            int kk = half * HALF_VEC + k;
            float4 w0 = w0v[kk];
            float4 w1 = w1v[kk];
            float4 w2 = w2v[kk];
            acc0 += d.x * w0.x + d.y * w0.y + d.z * w0.z + d.w * w0.w;
            acc1 += d.x * w1.x + d.y * w1.y + d.z * w1.z + d.w * w1.w;
            acc2 += d.x * w2.x + d.y * w2.y + d.z * w2.z + d.w * w2.w;
        }

        if (half == 1 && live) {
            float p0 = acc0 + sb[0];
            float p1 = acc1 + sb[1];
            float p2 = acc2 + sb[2];

            float n = sqrtf(p0 * p0 + p1 * p1 + p2 * p2);
            float inv = 1.0f / fmaxf(n, EPS);
            float pn0 = p0 * inv, pn1 = p1 * inv, pn2 = p2 * inv;

            float dot = pn0 * l0 + pn1 * l1 + pn2 * l2;
            float na = fmaxf(sqrtf(pn0 * pn0 + pn1 * pn1 + pn2 * pn2), EPS);
            float nb = fmaxf(sqrtf(l0 * l0 + l1 * l1 + l2 * l2), EPS);
            float cosv = dot / (na * nb);

            float loss = acosf(cosv) * RAD2DEG;
            if (isnan(loss)) loss = 0.0f;
            out[cur_row] = loss;
        }

        __syncthreads();   // everyone done reading buffer (item&1)

        int nxt = item + 2;
        if (nxt < nitems) prefetch(nxt);
        else              cp_commit();   // keep group accounting uniform
    }
}

extern "C" void kernel_launch(void* const* d_in, const int* in_sizes, int n_in,
                              void* d_out, int out_size)
{
    const float* data = (const float*)d_in[0];
    const float* lab  = (const float*)d_in[1];
    const float* W    = (const float*)d_in[2];
    const float* b    = (const float*)d_in[3];
    float* out = (float*)d_out;

    int N = in_sizes[0] / 64;
    int ntiles = (N + TILE_ROWS - 1) / TILE_ROWS;
    int blocks = 148 * 6;              // persistent: ~6 CTAs per SM
    if (blocks > ntiles) blocks = ntiles;
    cosine_loss_kernel<<<blocks, THREADS>>>(data, lab, W, b, out, N, ntiles);
}

// round 7
// speedup vs baseline: 2.2048x; 1.0532x over previous
#include <cuda_runtime.h>
#include <cstdint>
#include <math.h>

#define EPS 1e-8f
#define RAD2DEG 57.295779513082320876798154814105f

#define THREADS    128
#define TILE_ROWS  128
#define QCOLS      4          // float4 per row per quarter-tile (16 floats)
#define SSTRIDE    16         // floats per row (no pad; XOR swizzle instead)
#define NBUF       3          // ring depth (>= prefetch distance + 1)

// Inputs: data [N,64] f32, lab [N,3] f32, W [64,3] f32, b [3] f32 ; out [N] f32
//
// Persistent blocks, grid-stride over 128-row tiles, four 16-column
// quarter-tiles per tile staged via cp.async.cg into a 3-deep shared ring
// (prefetch distance 2, ONE __syncthreads per item). Bank conflicts avoided
// with an XOR swizzle on the float4 column slot: c' = c ^ ((row>>1)&3),
// keeping rows exactly 16 floats (64B) so 3 buffers fit in 24.6KB and
// 8 CTAs/SM are resident.

__device__ __forceinline__ void cp_async16(unsigned int dst, const void* src) {
    asm volatile("cp.async.cg.shared.global [%0], [%1], 16;\n"
                 :: "r"(dst), "l"(src));
}
__device__ __forceinline__ void cp_commit() {
    asm volatile("cp.async.commit_group;\n");
}
template <int n>
__device__ __forceinline__ void cp_wait() {
    asm volatile("cp.async.wait_group %0;\n" :: "n"(n));
}

__global__ __launch_bounds__(THREADS, 8) void cosine_loss_kernel(
    const float* __restrict__ data,
    const float* __restrict__ lab,
    const float* __restrict__ W,
    const float* __restrict__ b,
    float* __restrict__ out,
    int N, int ntiles)
{
    __shared__ __align__(16) float sbuf[NBUF][TILE_ROWS * SSTRIDE]; // 3 x 8KB
    __shared__ __align__(16) float sW[3][64];
    __shared__ float sb[3];

    const int t = threadIdx.x;

    // Stage W transposed to [3][64] and b (visible after first barrier).
    if (t < 192) { int k = t / 3, c = t % 3; sW[c][k] = W[t]; }
    {
        int i = t + 128;
        if (i < 192) { int k = i / 3, c = i % 3; sW[c][k] = W[i]; }
    }
    if (t < 3) sb[t] = b[t];

    // Items enumerate (tile-slot, quarter): item = 4*slot + q.
    const int nslots = (ntiles - blockIdx.x + (int)gridDim.x - 1) / (int)gridDim.x;
    const int nitems = 4 * nslots;
    if (nitems == 0) return;

    // Stage one (tile, quarter) item into sbuf[item % NBUF].
    auto prefetch = [&](int item) {
        int slot = item >> 2;
        int q    = item & 3;
        int tile = blockIdx.x + slot * gridDim.x;
        int row0 = tile * TILE_ROWS;
        const float4* gsrc = reinterpret_cast<const float4*>(data);
        unsigned int sdst =
            (unsigned int)__cvta_generic_to_shared(&sbuf[item % NBUF][0]);
        #pragma unroll
        for (int j = 0; j < QCOLS; ++j) {
            int v = j * THREADS + t;          // 0..511 float4s in quarter-tile
            int r = v >> 2;                   // local row
            int c = v & 3;                    // float4 within quarter-row
            int cs = c ^ ((r >> 1) & 3);      // swizzled column slot
            int row = row0 + r;
            if (row < N) {
                const float4* src = &gsrc[(size_t)row * 16 + q * QCOLS + c];
                cp_async16(sdst + (unsigned int)((r * SSTRIDE + cs * 4) * 4), src);
            }
        }
        cp_commit();
    };

    // Prime the pipeline (distance 2).
    prefetch(0);
    if (nitems > 1) prefetch(1); else cp_commit();

    const float4* __restrict__ w0v = reinterpret_cast<const float4*>(sW[0]);
    const float4* __restrict__ w1v = reinterpret_cast<const float4*>(sW[1]);
    const float4* __restrict__ w2v = reinterpret_cast<const float4*>(sW[2]);

    const int myswz = (t >> 1) & 3;           // this thread's row swizzle

    float acc0 = 0.f, acc1 = 0.f, acc2 = 0.f;
    float l0 = 0.f, l1 = 0.f, l2 = 0.f;
    int cur_row = -1;

    for (int item = 0; item < nitems; ++item) {
        cp_wait<1>();
        __syncthreads();   // buffer (item % NBUF) staged; prior reads retired

        const int slot = item >> 2;
        const int q    = item & 3;
        const int tile = blockIdx.x + slot * gridDim.x;
        const int row  = tile * TILE_ROWS + t;
        const bool live = (row < N);

        const float4* __restrict__ dv =
            reinterpret_cast<const float4*>(&sbuf[item % NBUF][t * SSTRIDE]);

        if (q == 0) {
            acc0 = acc1 = acc2 = 0.f;
            cur_row = row;
            if (live) {
                const float* lr = lab + (size_t)row * 3;
                l0 = __ldg(&lr[0]); l1 = __ldg(&lr[1]); l2 = __ldg(&lr[2]);
            }
        }

        #pragma unroll
        for (int k = 0; k < QCOLS; ++k) {
            float4 d  = dv[k ^ myswz];        // undo swizzle
            int kk = q * QCOLS + k;
            float4 w0 = w0v[kk];
            float4 w1 = w1v[kk];
            float4 w2 = w2v[kk];
            acc0 += d.x * w0.x + d.y * w0.y + d.z * w0.z + d.w * w0.w;
            acc1 += d.x * w1.x + d.y * w1.y + d.z * w1.z + d.w * w1.w;
            acc2 += d.x * w2.x + d.y * w2.y + d.z * w2.z + d.w * w2.w;
        }

        if (q == 3 && live) {
            float p0 = acc0 + sb[0];
            float p1 = acc1 + sb[1];
            float p2 = acc2 + sb[2];

            float n = sqrtf(p0 * p0 + p1 * p1 + p2 * p2);
            float inv = 1.0f / fmaxf(n, EPS);
            float pn0 = p0 * inv, pn1 = p1 * inv, pn2 = p2 * inv;

            float dot = pn0 * l0 + pn1 * l1 + pn2 * l2;
            float na = fmaxf(sqrtf(pn0 * pn0 + pn1 * pn1 + pn2 * pn2), EPS);
            float nb = fmaxf(sqrtf(l0 * l0 + l1 * l1 + l2 * l2), EPS);
            float cosv = dot / (na * nb);

            float loss = acosf(cosv) * RAD2DEG;
            if (isnan(loss)) loss = 0.0f;
            out[cur_row] = loss;
        }

        // No trailing barrier: ring depth 3 >= distance 2 + 1, so the target
        // buffer's last readers are already ordered by the barrier above.
        int nxt = item + 2;
        if (nxt < nitems) prefetch(nxt);
        else              cp_commit();   // keep group accounting uniform
    }
}

extern "C" void kernel_launch(void* const* d_in, const int* in_sizes, int n_in,
                              void* d_out, int out_size)
{
    const float* data = (const float*)d_in[0];
    const float* lab  = (const float*)d_in[1];
    const float* W    = (const float*)d_in[2];
    const float* b    = (const float*)d_in[3];
    float* out = (float*)d_out;

    int N = in_sizes[0] / 64;
    int ntiles = (N + TILE_ROWS - 1) / TILE_ROWS;
    int blocks = 148 * 8;              // persistent: 8 CTAs per SM target
    if (blocks > ntiles) blocks = ntiles;
    cosine_loss_kernel<<<blocks, THREADS>>>(data, lab, W, b, out, N, ntiles);
}